// round 2
// baseline (speedup 1.0000x reference)
#include <cuda_runtime.h>
#include <math.h>

#define NN   100000
#define NG   1000
#define NS   100
#define NE   99000
#define FIN  512
#define HIDD 128
#define FO   64

// ---------------- scratch (device globals; no allocations allowed) ----------------
__device__ __align__(16) float g_hx[NN * FIN];          // adapter output, overwritten by z in-place
__device__ __align__(16) float g_t1td[NN * HIDD];
__device__ __align__(16) float g_t1bu[NN * HIDD];
__device__ __align__(16) float g_h1td[NN * HIDD];
__device__ __align__(16) float g_h1bu[NN * HIDD];
__device__ __align__(16) float g_t2td[NN * FO];
__device__ __align__(16) float g_t2bu[NN * FO];
__device__ __align__(16) float g_tp[2 * NG * HIDD];     // prompt pre-LN
__device__ __align__(16) float g_tln[2 * NG * HIDD];    // tanh(graph_ln(...))
__device__ __align__(16) float g_pm[2 * NG * FIN];      // p_mul (0), p_add (1)
__device__ __align__(16) float g_hcat[NG * 128];
__device__ __align__(16) float g_r1[NG * 256];
__device__ __align__(16) float g_alpha[NG];
__device__ __align__(16) float g_stats[4];              // S1,S2 for prompt1; S1,S2 for prompt2
__device__ __align__(16) int   g_cnt[NN];               // children count per node
__device__ __align__(16) int   g_parent[NN];
__device__ int   g_idx64;                               // 1 if index arrays are int64

// ---------------- index dtype probe + edge accessors ----------------
__global__ void k_detect(const int* batch) {
    if (threadIdx.x == 0) g_idx64 = (batch[150] == 1) ? 0 : 1;
}
__device__ __forceinline__ int esrc(const void* ei, int e) {
    return g_idx64 ? (int)((const long long*)ei)[e] : ((const int*)ei)[e];
}
__device__ __forceinline__ int edst(const void* ei, int e) {
    return g_idx64 ? (int)((const long long*)ei)[NE + e] : ((const int*)ei)[NE + e];
}

// ---------------- small kernels ----------------
__global__ void k_zero() {
    int i = blockIdx.x * blockDim.x + threadIdx.x;
    if (i < NN) g_cnt[i] = 0;
    if (i < 4) g_stats[i] = 0.f;
}

__global__ void k_count(const void* ei) {
    int e = blockIdx.x * blockDim.x + threadIdx.x;
    if (e >= NE) return;
    int s = esrc(ei, e), d = edst(ei, e);
    atomicAdd(&g_cnt[s], 1);
    g_parent[d] = s;
}

__global__ void k_alpha() {
    int g = blockIdx.x * blockDim.x + threadIdx.x;
    if (g >= NG) return;
    float cnt = (float)g_cnt[g * NS];           // root's children
    float t = (cnt / (float)NS - 0.3f) / 0.1f;
    g_alpha[g] = 1.f / (1.f + expf(-t));
}

// ---------------- SGEMM: C[M,N] = A[M,K] @ B[K,N] (+bias, +act) ----------------
// BM=128, BK=16, 256 threads, thread tile TM=8 x TN; BN = 16*TN.
template <int BN, int TN, int ACT>
__global__ void __launch_bounds__(256) sgemm128(
    const float* __restrict__ A, const float* __restrict__ B,
    const float* __restrict__ bias, float* __restrict__ C,
    int M, int Nn, int K)
{
    constexpr int BM = 128, BK = 16, TM = 8;
    __shared__ __align__(16) float As[BK][BM];
    __shared__ __align__(16) float Bs[BK][BN];
    const int tid = threadIdx.x;
    const int tx = tid & 15, ty = tid >> 4;
    const int bm0 = blockIdx.y * BM, bn0 = blockIdx.x * BN;
    const int m0 = ty * TM, n0 = tx * TN;

    float acc[TM][TN];
#pragma unroll
    for (int i = 0; i < TM; i++)
#pragma unroll
        for (int j = 0; j < TN; j++) acc[i][j] = 0.f;

    for (int k0 = 0; k0 < K; k0 += BK) {
#pragma unroll
        for (int i = 0; i < 2; i++) {               // A tile: 512 float4
            int idx = tid + i * 256;
            int r = idx >> 2, kq = (idx & 3) << 2;
            float4 v = make_float4(0.f, 0.f, 0.f, 0.f);
            int gr = bm0 + r;
            if (gr < M) v = *reinterpret_cast<const float4*>(A + (size_t)gr * K + k0 + kq);
            As[kq + 0][r] = v.x; As[kq + 1][r] = v.y;
            As[kq + 2][r] = v.z; As[kq + 3][r] = v.w;
        }
#pragma unroll
        for (int i = 0; i < BN / 64; i++) {         // B tile
            int idx = tid + i * 256;
            int r = idx / (BN / 4), c4 = idx % (BN / 4);
            *reinterpret_cast<float4*>(&Bs[r][c4 * 4]) =
                *reinterpret_cast<const float4*>(B + (size_t)(k0 + r) * Nn + bn0 + c4 * 4);
        }
        __syncthreads();
#pragma unroll
        for (int kk = 0; kk < BK; kk++) {
            float a[TM], b[TN];
            *(float4*)&a[0] = *(const float4*)&As[kk][m0];
            *(float4*)&a[4] = *(const float4*)&As[kk][m0 + 4];
#pragma unroll
            for (int j = 0; j < TN; j += 4)
                *(float4*)&b[j] = *(const float4*)&Bs[kk][n0 + j];
#pragma unroll
            for (int i = 0; i < TM; i++)
#pragma unroll
                for (int j = 0; j < TN; j++)
                    acc[i][j] = fmaf(a[i], b[j], acc[i][j]);
        }
        __syncthreads();
    }

    float bv[TN];
#pragma unroll
    for (int j = 0; j < TN; j++) bv[j] = bias ? bias[bn0 + n0 + j] : 0.f;
#pragma unroll
    for (int i = 0; i < TM; i++) {
        int gr = bm0 + m0 + i;
        if (gr >= M) continue;
#pragma unroll
        for (int j4 = 0; j4 < TN; j4 += 4) {
            float4 v;
            float t;
            t = acc[i][j4 + 0] + bv[j4 + 0]; if (ACT == 1) t = t > 0.f ? t : 0.01f * t; v.x = t;
            t = acc[i][j4 + 1] + bv[j4 + 1]; if (ACT == 1) t = t > 0.f ? t : 0.01f * t; v.y = t;
            t = acc[i][j4 + 2] + bv[j4 + 2]; if (ACT == 1) t = t > 0.f ? t : 0.01f * t; v.z = t;
            t = acc[i][j4 + 3] + bv[j4 + 3]; if (ACT == 1) t = t > 0.f ? t : 0.01f * t; v.w = t;
            *reinterpret_cast<float4*>(C + (size_t)gr * Nn + bn0 + n0 + j4) = v;
        }
    }
}

// ---------------- prompt kernels ----------------
// t[g][j] = root_feat[g] @ w1 + b1, plus global sum/sumsq accumulation
__global__ void k_promptA(const float* __restrict__ w1a, const float* __restrict__ b1a,
                          const float* __restrict__ w1b, const float* __restrict__ b1b)
{
    int g = blockIdx.x, which = blockIdx.y, j = threadIdx.x; // 128 threads
    const float* w = which ? w1b : w1a;
    const float* b = which ? b1b : b1a;
    const float* rf = g_hx + (size_t)(g * NS) * FIN;
    float acc = b[j];
#pragma unroll 4
    for (int k = 0; k < FIN; k++) acc = fmaf(rf[k], w[k * HIDD + j], acc);
    g_tp[which * NG * HIDD + g * HIDD + j] = acc;

    __shared__ float s1[128], s2[128];
    s1[j] = acc; s2[j] = acc * acc;
    __syncthreads();
    for (int o = 64; o > 0; o >>= 1) {
        if (j < o) { s1[j] += s1[j + o]; s2[j] += s2[j + o]; }
        __syncthreads();
    }
    if (j == 0) {
        atomicAdd(&g_stats[which * 2 + 0], s1[0]);
        atomicAdd(&g_stats[which * 2 + 1], s2[0]);
    }
}

__global__ void k_promptLN(const float* __restrict__ lnwa, const float* __restrict__ lnba,
                           const float* __restrict__ lnwb, const float* __restrict__ lnbb)
{
    int g = blockIdx.x, which = blockIdx.y, j = threadIdx.x;
    const float* lw = which ? lnwb : lnwa;
    const float* lb = which ? lnbb : lnba;
    const float inv_n = 1.f / (float)(NG * HIDD);
    float m = g_stats[which * 2 + 0] * inv_n;
    float msq = fmaxf(g_stats[which * 2 + 1] * inv_n - m * m, 0.f);
    float denom = sqrtf(msq) + 1e-5f;
    float t = g_tp[which * NG * HIDD + g * HIDD + j];
    float v = (t - m) / denom * lw[j] + lb[j];
    g_tln[which * NG * HIDD + g * HIDD + j] = tanhf(v);
}

__global__ void k_promptB(const float* __restrict__ w2a, const float* __restrict__ b2a,
                          const float* __restrict__ w2b, const float* __restrict__ b2b)
{
    int g = blockIdx.x, which = blockIdx.y, j = threadIdx.x; // 512 threads
    const float* w = which ? w2b : w2a;
    const float* b = which ? b2b : b2a;
    const float* t = g_tln + which * NG * HIDD + g * HIDD;
    float acc = b[j];
#pragma unroll 4
    for (int k = 0; k < HIDD; k++) acc = fmaf(t[k], w[k * FIN + j], acc);
    g_pm[which * NG * FIN + g * FIN + j] = acc;
}

// z = (1-alpha)*(hx*p_mul) + alpha*(hx+p_add), in-place on g_hx
__global__ void k_z() {
    int idx = blockIdx.x * blockDim.x + threadIdx.x;      // over NN*FIN/4
    int node = idx / (FIN / 4), q = idx % (FIN / 4);
    int g = node / NS;
    float a = g_alpha[g];
    float4 h = reinterpret_cast<float4*>(g_hx)[idx];
    float4 pm = reinterpret_cast<const float4*>(g_pm)[g * (FIN / 4) + q];
    float4 pa = reinterpret_cast<const float4*>(g_pm + NG * FIN)[g * (FIN / 4) + q];
    float4 o;
    o.x = (1.f - a) * (h.x * pm.x) + a * (h.x + pa.x);
    o.y = (1.f - a) * (h.y * pm.y) + a * (h.y + pa.y);
    o.z = (1.f - a) * (h.z * pm.z) + a * (h.z + pa.z);
    o.w = (1.f - a) * (h.w * pm.w) + a * (h.w + pa.w);
    reinterpret_cast<float4*>(g_hx)[idx] = o;
}

// ---------------- GCN aggregation ----------------
// TD layer 1: each non-root receives exactly one message (from parent). relu + bias.
__global__ void k_td_agg1(const float* __restrict__ bias) {
    int idx = blockIdx.x * blockDim.x + threadIdx.x; // NN*HIDD
    int i = idx / HIDD, f = idx % HIDD;
    float self = g_t1td[idx];
    float v;
    if (i % NS == 0) {
        v = self;                                    // deg 1
    } else {
        int p = g_parent[i];
        float dp = (p % NS) ? 0.70710678118654752f : 1.0f;
        v = self * 0.5f + g_t1td[(size_t)p * HIDD + f] * dp * 0.70710678118654752f;
    }
    v += bias[f];
    g_h1td[idx] = v > 0.f ? v : 0.f;
}

// BU layer 1: per-graph block, 64 features per block (grid.y=2).
__global__ void k_bu_agg1(const void* __restrict__ ei, const float* __restrict__ bias) {
    __shared__ float outS[NS * 64];
    __shared__ float dinvS[NS];
    int g = blockIdx.x, foff = blockIdx.y * 64, f = threadIdx.x; // 64 threads
    for (int n = f; n < NS; n += 64)
        dinvS[n] = rsqrtf((float)(g_cnt[g * NS + n] + 1));
    __syncthreads();
    for (int n = 0; n < NS; n++) {
        float d = dinvS[n];
        outS[n * 64 + f] = g_t1bu[(size_t)(g * NS + n) * HIDD + foff + f] * d * d;
    }
    __syncthreads();
    for (int e = 0; e < NS - 1; e++) {
        int ge = g * (NS - 1) + e;
        int s = esrc(ei, ge) - g * NS;
        int d = edst(ei, ge) - g * NS;
        outS[s * 64 + f] += g_t1bu[(size_t)(g * NS + d) * HIDD + foff + f] * dinvS[d] * dinvS[s];
    }
    __syncthreads();
    float b = bias[foff + f];
    for (int n = 0; n < NS; n++) {
        float v = outS[n * 64 + f] + b;
        g_h1bu[(size_t)(g * NS + n) * HIDD + foff + f] = v > 0.f ? v : 0.f;
    }
}

// layer-2 aggregation fused with per-graph segment sum -> hcat = [BU_x | TD_x]
__global__ void k_final_agg(const void* __restrict__ ei,
                            const float* __restrict__ bu2_b, const float* __restrict__ td2_b) {
    __shared__ float dinvS[NS];
    int g = blockIdx.x, f = threadIdx.x; // 64 threads
    for (int n = f; n < NS; n += 64)
        dinvS[n] = rsqrtf((float)(g_cnt[g * NS + n] + 1));
    __syncthreads();
    float atd = 0.f, abu = 0.f;
    for (int n = 0; n < NS; n++) {
        int i = g * NS + n;
        float vt = g_t2td[(size_t)i * FO + f];
        float vb = g_t2bu[(size_t)i * FO + f];
        atd += vt * (n ? 0.5f : 1.0f);
        abu += vb * dinvS[n] * dinvS[n];
    }
    for (int e = 0; e < NS - 1; e++) {
        int ge = g * (NS - 1) + e;
        int s = esrc(ei, ge) - g * NS;
        int d = edst(ei, ge) - g * NS;
        float ds_td = s ? 0.70710678118654752f : 1.0f;
        atd += g_t2td[(size_t)(g * NS + s) * FO + f] * ds_td * 0.70710678118654752f;
        abu += g_t2bu[(size_t)(g * NS + d) * FO + f] * dinvS[d] * dinvS[s];
    }
    g_hcat[g * 128 + f]      = abu + (float)NS * bu2_b[f];
    g_hcat[g * 128 + 64 + f] = atd + (float)NS * td2_b[f];
}

// ---------------- final projection ----------------
__global__ void k_projA(const float* __restrict__ w1, const float* __restrict__ b1) {
    int g = blockIdx.x, j = threadIdx.x; // 256 threads
    __shared__ float sh[128];
    if (j < 128) sh[j] = g_hcat[g * 128 + j];
    __syncthreads();
    float acc = b1[j];
#pragma unroll 4
    for (int k = 0; k < 128; k++) acc = fmaf(sh[k], w1[k * 256 + j], acc);
    g_r1[g * 256 + j] = acc > 0.f ? acc : 0.f;
}

__global__ void k_projB(const float* __restrict__ w2, const float* __restrict__ b2,
                        float* __restrict__ out) {
    int g = blockIdx.x, j = threadIdx.x; // 128 threads
    __shared__ float sh[256];
    sh[j] = g_r1[g * 256 + j];
    sh[j + 128] = g_r1[g * 256 + 128 + j];
    __syncthreads();
    float acc = b2[j];
#pragma unroll 4
    for (int k = 0; k < 256; k++) acc = fmaf(sh[k], w2[k * 128 + j], acc);
    out[g * 128 + j] = acc;
}

// ---------------- launch ----------------
extern "C" void kernel_launch(void* const* d_in, const int* in_sizes, int n_in,
                              void* d_out, int out_size) {
    const float* x         = (const float*)d_in[0];
    const void*  ei        = d_in[1];
    const int*   batch     = (const int*)d_in[2];
    const float* adapter_w = (const float*)d_in[3];
    const float* adapter_b = (const float*)d_in[4];
    const float* p1_w1 = (const float*)d_in[5];
    const float* p1_b1 = (const float*)d_in[6];
    const float* p1_lnw = (const float*)d_in[7];
    const float* p1_lnb = (const float*)d_in[8];
    const float* p1_w2 = (const float*)d_in[9];
    const float* p1_b2 = (const float*)d_in[10];
    const float* p2_w1 = (const float*)d_in[11];
    const float* p2_b1 = (const float*)d_in[12];
    const float* p2_lnw = (const float*)d_in[13];
    const float* p2_lnb = (const float*)d_in[14];
    const float* p2_w2 = (const float*)d_in[15];
    const float* p2_b2 = (const float*)d_in[16];
    const float* td1_w = (const float*)d_in[17];
    const float* td1_b = (const float*)d_in[18];
    const float* td2_w = (const float*)d_in[19];
    const float* td2_b = (const float*)d_in[20];
    const float* bu1_w = (const float*)d_in[21];
    const float* bu1_b = (const float*)d_in[22];
    const float* bu2_w = (const float*)d_in[23];
    const float* bu2_b = (const float*)d_in[24];
    const float* proj_w1 = (const float*)d_in[25];
    const float* proj_b1 = (const float*)d_in[26];
    const float* proj_w2 = (const float*)d_in[27];
    const float* proj_b2 = (const float*)d_in[28];
    float* out = (float*)d_out;
    (void)in_sizes; (void)n_in; (void)out_size;

    // Resolve REAL device addresses of the __device__ scratch arrays.
    // (Passing the symbol directly from host code passes the host shadow address,
    //  which on GB300/ATS is silently readable/writable host memory -> zeros bug.)
    float *p_hx, *p_t1td, *p_t1bu, *p_h1td, *p_h1bu, *p_t2td, *p_t2bu;
    cudaGetSymbolAddress((void**)&p_hx,   g_hx);
    cudaGetSymbolAddress((void**)&p_t1td, g_t1td);
    cudaGetSymbolAddress((void**)&p_t1bu, g_t1bu);
    cudaGetSymbolAddress((void**)&p_h1td, g_h1td);
    cudaGetSymbolAddress((void**)&p_h1bu, g_h1bu);
    cudaGetSymbolAddress((void**)&p_t2td, g_t2td);
    cudaGetSymbolAddress((void**)&p_t2bu, g_t2bu);

    const int MB = (NN + 127) / 128; // 782

    k_detect<<<1, 32>>>(batch);
    k_zero<<<(NN + 255) / 256, 256>>>();
    k_count<<<(NE + 255) / 256, 256>>>(ei);
    k_alpha<<<(NG + 127) / 128, 128>>>();

    // adapter: hx = leaky_relu(x @ Wa + ba)
    sgemm128<128, 8, 1><<<dim3(FIN / 128, MB), 256>>>(x, adapter_w, adapter_b, p_hx, NN, FIN, FIN);

    // prompts on roots
    k_promptA<<<dim3(NG, 2), 128>>>(p1_w1, p1_b1, p2_w1, p2_b1);
    k_promptLN<<<dim3(NG, 2), 128>>>(p1_lnw, p1_lnb, p2_lnw, p2_lnb);
    k_promptB<<<dim3(NG, 2), 512>>>(p1_w2, p1_b2, p2_w2, p2_b2);

    // z (in-place on g_hx)
    k_z<<<(NN * FIN / 4 + 255) / 256, 256>>>();

    // GCN layer 1 linear
    sgemm128<128, 8, 0><<<dim3(1, MB), 256>>>(p_hx, td1_w, nullptr, p_t1td, NN, HIDD, FIN);
    sgemm128<128, 8, 0><<<dim3(1, MB), 256>>>(p_hx, bu1_w, nullptr, p_t1bu, NN, HIDD, FIN);

    // layer-1 aggregation + relu + bias
    k_td_agg1<<<NN * HIDD / 256, 256>>>(td1_b);
    k_bu_agg1<<<dim3(NG, 2), 64>>>(ei, bu1_b);

    // GCN layer 2 linear
    sgemm128<64, 4, 0><<<dim3(1, MB), 256>>>(p_h1td, td2_w, nullptr, p_t2td, NN, FO, HIDD);
    sgemm128<64, 4, 0><<<dim3(1, MB), 256>>>(p_h1bu, bu2_w, nullptr, p_t2bu, NN, FO, HIDD);

    // layer-2 aggregation fused with segment sum
    k_final_agg<<<NG, 64>>>(ei, bu2_b, td2_b);

    // projection head
    k_projA<<<NG, 256>>>(proj_w1, proj_b1);
    k_projB<<<NG, 128>>>(proj_w2, proj_b2, out);
}

// round 4
// speedup vs baseline: 1.8685x; 1.8685x over previous
#include <cuda_runtime.h>
#include <cuda_bf16.h>
#include <math.h>
#include <stdint.h>

#define NN   100000
#define NNP  100096      // 782 * 128
#define NG   1000
#define NS   100
#define NE   99000
#define FIN  512
#define HIDD 128
#define FO   64

// ---------------- scratch (device globals; no allocations allowed) ----------------
__device__ __align__(16) float g_hx[NNP * FIN];                 // adapter output (fp32)
__device__ __align__(16) __nv_bfloat16 g_zh[NNP * FIN];         // z hi (bf16)
__device__ __align__(16) __nv_bfloat16 g_zl[NNP * FIN];         // z lo (bf16)
__device__ __align__(16) float g_cat1[NNP * 256];               // [td1 | bu1] GEMM output
__device__ __align__(16) float g_h1td[NNP * HIDD];
__device__ __align__(16) float g_h1bu[NNP * HIDD];
__device__ __align__(16) float g_t2td[NNP * FO];
__device__ __align__(16) float g_t2bu[NNP * FO];
__device__ __align__(16) __nv_bfloat16 g_waT_hi[FIN * FIN], g_waT_lo[FIN * FIN];    // adapter W^T [512][512]
__device__ __align__(16) __nv_bfloat16 g_wcT_hi[256 * FIN], g_wcT_lo[256 * FIN];    // [td1|bu1]^T [256][512]
__device__ __align__(16) __nv_bfloat16 g_w2td_hi[FO * HIDD], g_w2td_lo[FO * HIDD];  // td2^T [64][128]
__device__ __align__(16) __nv_bfloat16 g_w2bu_hi[FO * HIDD], g_w2bu_lo[FO * HIDD];
__device__ __align__(16) float g_tp[2 * NG * HIDD];
__device__ __align__(16) float g_tln[2 * NG * HIDD];
__device__ __align__(16) float g_pm[2 * NG * FIN];
__device__ __align__(16) float g_hcat[NG * 128];
__device__ __align__(16) float g_r1[NG * 256];
__device__ __align__(16) float g_alpha[NG];
__device__ __align__(16) float g_stats[4];
__device__ __align__(16) int   g_cnt[NN];
__device__ __align__(16) int   g_parent[NN];
__device__ int   g_idx64;

// ---------------- helpers ----------------
static __device__ __forceinline__ uint32_t smem_u32(const void* p) {
    uint32_t a;
    asm("{ .reg .u64 t; cvta.to.shared.u64 t, %1; cvt.u32.u64 %0, t; }" : "=r"(a) : "l"(p));
    return a;
}
#define CP_ASYNC16(dst_u32, src) \
    asm volatile("cp.async.cg.shared.global [%0], [%1], 16;" :: "r"(dst_u32), "l"(src))
#define CP_COMMIT() asm volatile("cp.async.commit_group;" ::: "memory")
#define CP_WAIT1()  asm volatile("cp.async.wait_group 1;" ::: "memory")
#define CP_WAIT0()  asm volatile("cp.async.wait_group 0;" ::: "memory")

#define MMA_BF16(d, a, b) \
    asm volatile("mma.sync.aligned.m16n8k16.row.col.f32.bf16.bf16.f32 " \
        "{%0,%1,%2,%3}, {%4,%5,%6,%7}, {%8,%9}, {%0,%1,%2,%3};" \
        : "+f"((d)[0]), "+f"((d)[1]), "+f"((d)[2]), "+f"((d)[3]) \
        : "r"((a)[0]), "r"((a)[1]), "r"((a)[2]), "r"((a)[3]), "r"((b)[0]), "r"((b)[1]))

// ---------------- index dtype probe + edge accessors ----------------
__global__ void k_detect(const int* batch) {
    if (threadIdx.x == 0) g_idx64 = (batch[150] == 1) ? 0 : 1;
}
__device__ __forceinline__ int esrc(const void* ei, int e) {
    return g_idx64 ? (int)((const long long*)ei)[e] : ((const int*)ei)[e];
}
__device__ __forceinline__ int edst(const void* ei, int e) {
    return g_idx64 ? (int)((const long long*)ei)[NE + e] : ((const int*)ei)[NE + e];
}

// ---------------- small graph kernels ----------------
__global__ void k_zero() {
    int i = blockIdx.x * blockDim.x + threadIdx.x;
    if (i < NN) g_cnt[i] = 0;
    if (i < 4) g_stats[i] = 0.f;
}
__global__ void k_count(const void* ei) {
    int e = blockIdx.x * blockDim.x + threadIdx.x;
    if (e >= NE) return;
    int s = esrc(ei, e), d = edst(ei, e);
    atomicAdd(&g_cnt[s], 1);
    g_parent[d] = s;
}
__global__ void k_alpha() {
    int g = blockIdx.x * blockDim.x + threadIdx.x;
    if (g >= NG) return;
    float cnt = (float)g_cnt[g * NS];
    float t = (cnt / (float)NS - 0.3f) / 0.1f;
    g_alpha[g] = 1.f / (1.f + expf(-t));
}

// ---------------- weight prep: transpose + bf16 hi/lo split ----------------
__global__ void k_wprep(const float* __restrict__ w, __nv_bfloat16* __restrict__ hi,
                        __nv_bfloat16* __restrict__ lo, int K, int Nw) {
    int i = blockIdx.x * blockDim.x + threadIdx.x;
    if (i >= K * Nw) return;
    int k = i / Nw, n = i % Nw;
    float v = w[i];
    __nv_bfloat16 h = __float2bfloat16(v);
    float r = v - __bfloat162float(h);
    hi[(size_t)n * K + k] = h;
    lo[(size_t)n * K + k] = __float2bfloat16(r);
}

// ---------------- HMMA GEMM: C[M][Ntot] = A[M][K] @ B^T, 3xBF16 split ----------------
// A: fp32 [M][K] (AF32=1, converted in-kernel) or bf16 hi/lo arrays (AF32=0).
// B: bf16 hi/lo [Ntot][K] (pre-transposed weights).
// CTA tile: 128 x BN, BK=32, double-buffered SMEM, cp.async staging.
// SMEM row stride 40 bf16 (80B) -> conflict-free 32-bit fragment loads.
template <int BN, int ACT, int AF32>
__global__ void __launch_bounds__(256) mmagemm(
    const float* __restrict__ A32,
    const __nv_bfloat16* __restrict__ Ah16, const __nv_bfloat16* __restrict__ Al16,
    const __nv_bfloat16* __restrict__ Bh, const __nv_bfloat16* __restrict__ Bl,
    const float* __restrict__ bias, float* __restrict__ C,
    int Ntot, int K, int Mlim)
{
    constexpr int ASZ = 128 * 40;       // elems per A stage (hi or lo)
    constexpr int BSZ = BN * 40;
    constexpr int MT  = (BN == 128) ? 2 : 1;
    extern __shared__ __align__(16) __nv_bfloat16 sm[];
    __nv_bfloat16* sAh = sm;
    __nv_bfloat16* sAl = sm + 2 * ASZ;
    __nv_bfloat16* sBh = sm + 4 * ASZ;
    __nv_bfloat16* sBl = sm + 4 * ASZ + 2 * BSZ;

    const int tid = threadIdx.x, lane = tid & 31, w = tid >> 5;
    const int m0 = blockIdx.y * 128, n0 = blockIdx.x * BN;
    const int warpM = (BN == 128) ? (w & 3) * 32 : w * 16;
    const int warpN = (BN == 128) ? (w >> 2) * 64 : 0;
    const int r4 = lane >> 2, q = lane & 3;

    float acc[MT][8][4];
#pragma unroll
    for (int mt = 0; mt < MT; mt++)
#pragma unroll
        for (int nt = 0; nt < 8; nt++)
#pragma unroll
            for (int i = 0; i < 4; i++) acc[mt][nt][i] = 0.f;

    const int KS = K >> 5;

    // ---- staging helpers ----
    // B: BN rows x 32 k (64B) per array; 16B chunks
    auto stageB = [&](int ks, int s) {
#pragma unroll
        for (int c = tid; c < BN * 4; c += 256) {
            int r = c >> 2, qq = c & 3;
            const __nv_bfloat16* sh = Bh + (size_t)(n0 + r) * K + ks * 32 + qq * 8;
            const __nv_bfloat16* sl = Bl + (size_t)(n0 + r) * K + ks * 32 + qq * 8;
            CP_ASYNC16(smem_u32(sBh + s * BSZ + r * 40) + qq * 16, sh);
            CP_ASYNC16(smem_u32(sBl + s * BSZ + r * 40) + qq * 16, sl);
        }
    };
    auto stageA16 = [&](int ks, int s) {
#pragma unroll
        for (int c = tid; c < 512; c += 256) {
            int r = c >> 2, qq = c & 3;
            const __nv_bfloat16* sh = Ah16 + (size_t)(m0 + r) * K + ks * 32 + qq * 8;
            const __nv_bfloat16* sl = Al16 + (size_t)(m0 + r) * K + ks * 32 + qq * 8;
            CP_ASYNC16(smem_u32(sAh + s * ASZ + r * 40) + qq * 16, sh);
            CP_ASYNC16(smem_u32(sAl + s * ASZ + r * 40) + qq * 16, sl);
        }
    };
    // fp32 A: each thread owns 16 floats: row = tid>>1, kg = (tid&1)*16
    const int ar = tid >> 1, akg = (tid & 1) * 16;
    float areg[16];
    auto loadA32 = [&](int ks) {
        const float* src = A32 + (size_t)(m0 + ar) * K + ks * 32 + akg;
        if (m0 + ar < Mlim) {
#pragma unroll
            for (int i = 0; i < 4; i++) {
                float4 v = *(const float4*)(src + i * 4);
                areg[i * 4 + 0] = v.x; areg[i * 4 + 1] = v.y;
                areg[i * 4 + 2] = v.z; areg[i * 4 + 3] = v.w;
            }
        } else {
#pragma unroll
            for (int i = 0; i < 16; i++) areg[i] = 0.f;
        }
    };
    auto storeA32 = [&](int s) {
        union { __nv_bfloat16 b[16]; uint4 u[2]; } H, L;
#pragma unroll
        for (int i = 0; i < 16; i++) {
            __nv_bfloat16 h = __float2bfloat16(areg[i]);
            H.b[i] = h;
            L.b[i] = __float2bfloat16(areg[i] - __bfloat162float(h));
        }
        uint4* dh = (uint4*)(sAh + s * ASZ + ar * 40 + akg);
        uint4* dl = (uint4*)(sAl + s * ASZ + ar * 40 + akg);
        dh[0] = H.u[0]; dh[1] = H.u[1];
        dl[0] = L.u[0]; dl[1] = L.u[1];
    };

    // ---- prologue ----
    if (AF32) loadA32(0); else stageA16(0, 0);
    stageB(0, 0);
    CP_COMMIT();

    for (int ks = 0; ks < KS; ks++) {
        const int s = ks & 1;
        const bool nxt = (ks + 1 < KS);
        if (nxt) {
            if (!AF32) stageA16(ks + 1, s ^ 1);
            stageB(ks + 1, s ^ 1);
            CP_COMMIT();
        }
        if (AF32) {
            storeA32(s);
            if (nxt) loadA32(ks + 1);
        }
        if (nxt) CP_WAIT1(); else CP_WAIT0();
        __syncthreads();

        // ---- compute on stage s ----
#pragma unroll
        for (int k16 = 0; k16 < 2; k16++) {
            uint32_t ah[MT][4], al[MT][4];
#pragma unroll
            for (int mt = 0; mt < MT; mt++) {
                const __nv_bfloat16* ap = sAh + s * ASZ + (warpM + mt * 16 + r4) * 40 + k16 * 16 + q * 2;
                const __nv_bfloat16* lp = sAl + s * ASZ + (warpM + mt * 16 + r4) * 40 + k16 * 16 + q * 2;
                ah[mt][0] = *(const uint32_t*)ap;
                ah[mt][1] = *(const uint32_t*)(ap + 8 * 40);
                ah[mt][2] = *(const uint32_t*)(ap + 8);
                ah[mt][3] = *(const uint32_t*)(ap + 8 * 40 + 8);
                al[mt][0] = *(const uint32_t*)lp;
                al[mt][1] = *(const uint32_t*)(lp + 8 * 40);
                al[mt][2] = *(const uint32_t*)(lp + 8);
                al[mt][3] = *(const uint32_t*)(lp + 8 * 40 + 8);
            }
#pragma unroll
            for (int nt = 0; nt < 8; nt++) {
                const __nv_bfloat16* bp = sBh + s * BSZ + (warpN + nt * 8 + r4) * 40 + k16 * 16 + q * 2;
                const __nv_bfloat16* bq = sBl + s * BSZ + (warpN + nt * 8 + r4) * 40 + k16 * 16 + q * 2;
                uint32_t bh[2] = { *(const uint32_t*)bp, *(const uint32_t*)(bp + 8) };
                uint32_t bl[2] = { *(const uint32_t*)bq, *(const uint32_t*)(bq + 8) };
#pragma unroll
                for (int mt = 0; mt < MT; mt++) {
                    MMA_BF16(acc[mt][nt], ah[mt], bh);
                    MMA_BF16(acc[mt][nt], al[mt], bh);
                    MMA_BF16(acc[mt][nt], ah[mt], bl);
                }
            }
        }
        __syncthreads();
    }

    // ---- epilogue ----
#pragma unroll
    for (int mt = 0; mt < MT; mt++) {
#pragma unroll
        for (int nt = 0; nt < 8; nt++) {
            int row = m0 + warpM + mt * 16 + r4;
            int col = n0 + warpN + nt * 8 + q * 2;
            float v0 = acc[mt][nt][0], v1 = acc[mt][nt][1];
            float v2 = acc[mt][nt][2], v3 = acc[mt][nt][3];
            if (ACT) {
                float b0 = bias[col], b1 = bias[col + 1];
                v0 += b0; v1 += b1; v2 += b0; v3 += b1;
                v0 = v0 > 0.f ? v0 : 0.01f * v0;
                v1 = v1 > 0.f ? v1 : 0.01f * v1;
                v2 = v2 > 0.f ? v2 : 0.01f * v2;
                v3 = v3 > 0.f ? v3 : 0.01f * v3;
            }
            float2 lo2 = make_float2(v0, v1), hi2 = make_float2(v2, v3);
            *(float2*)(C + (size_t)row * Ntot + col) = lo2;
            *(float2*)(C + (size_t)(row + 8) * Ntot + col) = hi2;
        }
    }
}

// ---------------- prompt kernels ----------------
__global__ void k_promptA(const float* __restrict__ w1a, const float* __restrict__ b1a,
                          const float* __restrict__ w1b, const float* __restrict__ b1b) {
    int g = blockIdx.x, which = blockIdx.y, j = threadIdx.x;
    const float* w = which ? w1b : w1a;
    const float* b = which ? b1b : b1a;
    const float* rf = g_hx + (size_t)(g * NS) * FIN;
    float acc = b[j];
#pragma unroll 4
    for (int k = 0; k < FIN; k++) acc = fmaf(rf[k], w[k * HIDD + j], acc);
    g_tp[which * NG * HIDD + g * HIDD + j] = acc;
    __shared__ float s1[128], s2[128];
    s1[j] = acc; s2[j] = acc * acc;
    __syncthreads();
    for (int o = 64; o > 0; o >>= 1) {
        if (j < o) { s1[j] += s1[j + o]; s2[j] += s2[j + o]; }
        __syncthreads();
    }
    if (j == 0) {
        atomicAdd(&g_stats[which * 2 + 0], s1[0]);
        atomicAdd(&g_stats[which * 2 + 1], s2[0]);
    }
}
__global__ void k_promptLN(const float* __restrict__ lnwa, const float* __restrict__ lnba,
                           const float* __restrict__ lnwb, const float* __restrict__ lnbb) {
    int g = blockIdx.x, which = blockIdx.y, j = threadIdx.x;
    const float* lw = which ? lnwb : lnwa;
    const float* lb = which ? lnbb : lnba;
    const float inv_n = 1.f / (float)(NG * HIDD);
    float m = g_stats[which * 2 + 0] * inv_n;
    float msq = fmaxf(g_stats[which * 2 + 1] * inv_n - m * m, 0.f);
    float denom = sqrtf(msq) + 1e-5f;
    float t = g_tp[which * NG * HIDD + g * HIDD + j];
    float v = (t - m) / denom * lw[j] + lb[j];
    g_tln[which * NG * HIDD + g * HIDD + j] = tanhf(v);
}
__global__ void k_promptB(const float* __restrict__ w2a, const float* __restrict__ b2a,
                          const float* __restrict__ w2b, const float* __restrict__ b2b) {
    int g = blockIdx.x, which = blockIdx.y, j = threadIdx.x;
    const float* w = which ? w2b : w2a;
    const float* b = which ? b2b : b2a;
    const float* t = g_tln + which * NG * HIDD + g * HIDD;
    float acc = b[j];
#pragma unroll 4
    for (int k = 0; k < HIDD; k++) acc = fmaf(t[k], w[k * FIN + j], acc);
    g_pm[which * NG * FIN + g * FIN + j] = acc;
}

// z = (1-alpha)*(hx*p_mul) + alpha*(hx+p_add) -> bf16 hi/lo arrays
__global__ void k_z() {
    int idx = blockIdx.x * blockDim.x + threadIdx.x;      // over NN*FIN/4
    int node = idx / (FIN / 4), qd = idx % (FIN / 4);
    int g = node / NS;
    float a = g_alpha[g];
    float4 h = reinterpret_cast<const float4*>(g_hx)[idx];
    float4 pm = reinterpret_cast<const float4*>(g_pm)[g * (FIN / 4) + qd];
    float4 pa = reinterpret_cast<const float4*>(g_pm + NG * FIN)[g * (FIN / 4) + qd];
    float z0 = (1.f - a) * (h.x * pm.x) + a * (h.x + pa.x);
    float z1 = (1.f - a) * (h.y * pm.y) + a * (h.y + pa.y);
    float z2 = (1.f - a) * (h.z * pm.z) + a * (h.z + pa.z);
    float z3 = (1.f - a) * (h.w * pm.w) + a * (h.w + pa.w);
    union { __nv_bfloat16 b[4]; uint2 u; } H, L;
    float zv[4] = { z0, z1, z2, z3 };
#pragma unroll
    for (int i = 0; i < 4; i++) {
        __nv_bfloat16 hh = __float2bfloat16(zv[i]);
        H.b[i] = hh;
        L.b[i] = __float2bfloat16(zv[i] - __bfloat162float(hh));
    }
    reinterpret_cast<uint2*>(g_zh)[idx] = H.u;
    reinterpret_cast<uint2*>(g_zl)[idx] = L.u;
}

// ---------------- GCN aggregation (reads g_cat1: td at col 0, bu at col 128) ----------------
__global__ void k_td_agg1(const float* __restrict__ bias) {
    int idx = blockIdx.x * blockDim.x + threadIdx.x; // NN*HIDD
    int i = idx / HIDD, f = idx % HIDD;
    float self = g_cat1[(size_t)i * 256 + f];
    float v;
    if (i % NS == 0) {
        v = self;
    } else {
        int p = g_parent[i];
        float dp = (p % NS) ? 0.70710678118654752f : 1.0f;
        v = self * 0.5f + g_cat1[(size_t)p * 256 + f] * dp * 0.70710678118654752f;
    }
    v += bias[f];
    g_h1td[(size_t)i * HIDD + f] = v > 0.f ? v : 0.f;
}
__global__ void k_bu_agg1(const void* __restrict__ ei, const float* __restrict__ bias) {
    __shared__ float outS[NS * 64];
    __shared__ float dinvS[NS];
    int g = blockIdx.x, foff = blockIdx.y * 64, f = threadIdx.x;
    for (int n = f; n < NS; n += 64)
        dinvS[n] = rsqrtf((float)(g_cnt[g * NS + n] + 1));
    __syncthreads();
    for (int n = 0; n < NS; n++) {
        float d = dinvS[n];
        outS[n * 64 + f] = g_cat1[(size_t)(g * NS + n) * 256 + 128 + foff + f] * d * d;
    }
    __syncthreads();
    for (int e = 0; e < NS - 1; e++) {
        int ge = g * (NS - 1) + e;
        int s = esrc(ei, ge) - g * NS;
        int d = edst(ei, ge) - g * NS;
        outS[s * 64 + f] += g_cat1[(size_t)(g * NS + d) * 256 + 128 + foff + f] * dinvS[d] * dinvS[s];
    }
    __syncthreads();
    float b = bias[foff + f];
    for (int n = 0; n < NS; n++) {
        float v = outS[n * 64 + f] + b;
        g_h1bu[(size_t)(g * NS + n) * HIDD + foff + f] = v > 0.f ? v : 0.f;
    }
}

// layer-2 aggregation fused with per-graph segment sum -> hcat = [BU_x | TD_x]
__global__ void k_final_agg(const void* __restrict__ ei,
                            const float* __restrict__ bu2_b, const float* __restrict__ td2_b) {
    __shared__ float dinvS[NS];
    int g = blockIdx.x, f = threadIdx.x;
    for (int n = f; n < NS; n += 64)
        dinvS[n] = rsqrtf((float)(g_cnt[g * NS + n] + 1));
    __syncthreads();
    float atd = 0.f, abu = 0.f;
    for (int n = 0; n < NS; n++) {
        int i = g * NS + n;
        atd += g_t2td[(size_t)i * FO + f] * (n ? 0.5f : 1.0f);
        abu += g_t2bu[(size_t)i * FO + f] * dinvS[n] * dinvS[n];
    }
    for (int e = 0; e < NS - 1; e++) {
        int ge = g * (NS - 1) + e;
        int s = esrc(ei, ge) - g * NS;
        int d = edst(ei, ge) - g * NS;
        float ds_td = s ? 0.70710678118654752f : 1.0f;
        atd += g_t2td[(size_t)(g * NS + s) * FO + f] * ds_td * 0.70710678118654752f;
        abu += g_t2bu[(size_t)(g * NS + d) * FO + f] * dinvS[d] * dinvS[s];
    }
    g_hcat[g * 128 + f]      = abu + (float)NS * bu2_b[f];
    g_hcat[g * 128 + 64 + f] = atd + (float)NS * td2_b[f];
}

// ---------------- final projection ----------------
__global__ void k_projA(const float* __restrict__ w1, const float* __restrict__ b1) {
    int g = blockIdx.x, j = threadIdx.x; // 256 threads
    __shared__ float sh[128];
    if (j < 128) sh[j] = g_hcat[g * 128 + j];
    __syncthreads();
    float acc = b1[j];
#pragma unroll 4
    for (int k = 0; k < 128; k++) acc = fmaf(sh[k], w1[k * 256 + j], acc);
    g_r1[g * 256 + j] = acc > 0.f ? acc : 0.f;
}
__global__ void k_projB(const float* __restrict__ w2, const float* __restrict__ b2,
                        float* __restrict__ out) {
    int g = blockIdx.x, j = threadIdx.x; // 128 threads
    __shared__ float sh[256];
    sh[j] = g_r1[g * 256 + j];
    sh[j + 128] = g_r1[g * 256 + 128 + j];
    __syncthreads();
    float acc = b2[j];
#pragma unroll 4
    for (int k = 0; k < 256; k++) acc = fmaf(sh[k], w2[k * 128 + j], acc);
    out[g * 128 + j] = acc;
}

// ---------------- launch ----------------
extern "C" void kernel_launch(void* const* d_in, const int* in_sizes, int n_in,
                              void* d_out, int out_size) {
    const float* x         = (const float*)d_in[0];
    const void*  ei        = d_in[1];
    const int*   batch     = (const int*)d_in[2];
    const float* adapter_w = (const float*)d_in[3];
    const float* adapter_b = (const float*)d_in[4];
    const float* p1_w1 = (const float*)d_in[5];
    const float* p1_b1 = (const float*)d_in[6];
    const float* p1_lnw = (const float*)d_in[7];
    const float* p1_lnb = (const float*)d_in[8];
    const float* p1_w2 = (const float*)d_in[9];
    const float* p1_b2 = (const float*)d_in[10];
    const float* p2_w1 = (const float*)d_in[11];
    const float* p2_b1 = (const float*)d_in[12];
    const float* p2_lnw = (const float*)d_in[13];
    const float* p2_lnb = (const float*)d_in[14];
    const float* p2_w2 = (const float*)d_in[15];
    const float* p2_b2 = (const float*)d_in[16];
    const float* td1_w = (const float*)d_in[17];
    const float* td1_b = (const float*)d_in[18];
    const float* td2_w = (const float*)d_in[19];
    const float* td2_b = (const float*)d_in[20];
    const float* bu1_w = (const float*)d_in[21];
    const float* bu1_b = (const float*)d_in[22];
    const float* bu2_w = (const float*)d_in[23];
    const float* bu2_b = (const float*)d_in[24];
    const float* proj_w1 = (const float*)d_in[25];
    const float* proj_b1 = (const float*)d_in[26];
    const float* proj_w2 = (const float*)d_in[27];
    const float* proj_b2 = (const float*)d_in[28];
    float* out = (float*)d_out;
    (void)in_sizes; (void)n_in; (void)out_size;

    // real device addresses of scratch (host shadow symbols are NOT device pointers!)
    float *p_hx, *p_cat1, *p_h1td, *p_h1bu, *p_t2td, *p_t2bu;
    __nv_bfloat16 *p_zh, *p_zl;
    __nv_bfloat16 *p_waH, *p_waL, *p_wcH, *p_wcL, *p_w2tH, *p_w2tL, *p_w2bH, *p_w2bL;
    cudaGetSymbolAddress((void**)&p_hx,   g_hx);
    cudaGetSymbolAddress((void**)&p_cat1, g_cat1);
    cudaGetSymbolAddress((void**)&p_h1td, g_h1td);
    cudaGetSymbolAddress((void**)&p_h1bu, g_h1bu);
    cudaGetSymbolAddress((void**)&p_t2td, g_t2td);
    cudaGetSymbolAddress((void**)&p_t2bu, g_t2bu);
    cudaGetSymbolAddress((void**)&p_zh,   g_zh);
    cudaGetSymbolAddress((void**)&p_zl,   g_zl);
    cudaGetSymbolAddress((void**)&p_waH,  g_waT_hi);
    cudaGetSymbolAddress((void**)&p_waL,  g_waT_lo);
    cudaGetSymbolAddress((void**)&p_wcH,  g_wcT_hi);
    cudaGetSymbolAddress((void**)&p_wcL,  g_wcT_lo);
    cudaGetSymbolAddress((void**)&p_w2tH, g_w2td_hi);
    cudaGetSymbolAddress((void**)&p_w2tL, g_w2td_lo);
    cudaGetSymbolAddress((void**)&p_w2bH, g_w2bu_hi);
    cudaGetSymbolAddress((void**)&p_w2bL, g_w2bu_lo);

    // dynamic smem: (4*ASZ + 4*BSZ) bf16
    constexpr int SMEM128 = (4 * 128 * 40 + 4 * 128 * 40) * 2;   // 81920
    constexpr int SMEM64  = (4 * 128 * 40 + 4 * 64 * 40) * 2;    // 61440
    cudaFuncSetAttribute(mmagemm<128, 1, 1>, cudaFuncAttributeMaxDynamicSharedMemorySize, SMEM128);
    cudaFuncSetAttribute(mmagemm<128, 0, 0>, cudaFuncAttributeMaxDynamicSharedMemorySize, SMEM128);
    cudaFuncSetAttribute(mmagemm<64, 0, 1>,  cudaFuncAttributeMaxDynamicSharedMemorySize, SMEM64);

    const int MB = NNP / 128; // 782

    k_detect<<<1, 32>>>(batch);
    k_zero<<<(NN + 255) / 256, 256>>>();
    k_count<<<(NE + 255) / 256, 256>>>(ei);
    k_alpha<<<(NG + 127) / 128, 128>>>();

    // weight prep: transpose + bf16 split
    k_wprep<<<(FIN * FIN + 255) / 256, 256>>>(adapter_w, p_waH, p_waL, FIN, FIN);
    k_wprep<<<(FIN * HIDD + 255) / 256, 256>>>(td1_w, p_wcH, p_wcL, FIN, HIDD);
    k_wprep<<<(FIN * HIDD + 255) / 256, 256>>>(bu1_w, p_wcH + 128 * FIN, p_wcL + 128 * FIN, FIN, HIDD);
    k_wprep<<<(HIDD * FO + 255) / 256, 256>>>(td2_w, p_w2tH, p_w2tL, HIDD, FO);
    k_wprep<<<(HIDD * FO + 255) / 256, 256>>>(bu2_w, p_w2bH, p_w2bL, HIDD, FO);

    // adapter: hx = leaky_relu(x @ Wa + ba)   [HMMA, N=512 over 4 tiles]
    mmagemm<128, 1, 1><<<dim3(4, MB), 256, SMEM128>>>(
        x, nullptr, nullptr, p_waH, p_waL, adapter_b, p_hx, FIN, FIN, NN);

    // prompts on roots
    k_promptA<<<dim3(NG, 2), 128>>>(p1_w1, p1_b1, p2_w1, p2_b1);
    k_promptLN<<<dim3(NG, 2), 128>>>(p1_lnw, p1_lnb, p2_lnw, p2_lnb);
    k_promptB<<<dim3(NG, 2), 512>>>(p1_w2, p1_b2, p2_w2, p2_b2);

    // z -> bf16 hi/lo
    k_z<<<(NN * FIN / 4 + 255) / 256, 256>>>();

    // GCN layer 1 linear (td|bu concat, N=256), A = z bf16 hi/lo
    mmagemm<128, 0, 0><<<dim3(2, MB), 256, SMEM128>>>(
        nullptr, p_zh, p_zl, p_wcH, p_wcL, nullptr, p_cat1, 256, FIN, NNP);

    // layer-1 aggregation + relu + bias
    k_td_agg1<<<NN * HIDD / 256, 256>>>(td1_b);
    k_bu_agg1<<<dim3(NG, 2), 64>>>(ei, bu1_b);

    // GCN layer 2 linear
    mmagemm<64, 0, 1><<<dim3(1, MB), 256, SMEM64>>>(
        p_h1td, nullptr, nullptr, p_w2tH, p_w2tL, nullptr, p_t2td, FO, HIDD, NNP);
    mmagemm<64, 0, 1><<<dim3(1, MB), 256, SMEM64>>>(
        p_h1bu, nullptr, nullptr, p_w2bH, p_w2bL, nullptr, p_t2bu, FO, HIDD, NNP);

    // layer-2 aggregation fused with segment sum
    k_final_agg<<<NG, 64>>>(ei, bu2_b, td2_b);

    // projection head
    k_projA<<<NG, 256>>>(proj_w1, proj_b1);
    k_projB<<<NG, 128>>>(proj_w2, proj_b2, out);
}